// round 1
// baseline (speedup 1.0000x reference)
#include <cuda_runtime.h>

#define NB 8
#define NT 2048
#define NE 1024
#define ND 1024  // DK*H

// Scratch: __device__ globals (no allocation allowed in kernel_launch)
__device__ float g_Q[(size_t)NB * NT * ND];
__device__ float g_K[(size_t)NB * NT * ND];
__device__ float g_V[(size_t)NB * NT * ND];
__device__ float g_S[(size_t)NB * NT * NT];
__device__ int   g_len[NB];

// ---------------------------------------------------------------------------
// Per-batch valid length = number of nonzero rows of x[b]  (matches reference:
// count of nonzeros of energy[b,0,:], since K-row is zero iff x-row is zero)
// ---------------------------------------------------------------------------
__global__ __launch_bounds__(256) void len_k(const float* __restrict__ x)
{
    const int b = blockIdx.x;
    __shared__ int cnt;
    if (threadIdx.x == 0) cnt = 0;
    __syncthreads();
    int local = 0;
    for (int t = threadIdx.x; t < NT; t += blockDim.x) {
        const float4* row = (const float4*)(x + ((size_t)b * NT + t) * NE);
        bool nz = false;
        #pragma unroll 4
        for (int e = 0; e < NE / 4; e++) {
            float4 v = row[e];
            if (v.x != 0.f || v.y != 0.f || v.z != 0.f || v.w != 0.f) { nz = true; break; }
        }
        if (nz) local++;
    }
    atomicAdd(&cnt, local);
    __syncthreads();
    if (threadIdx.x == 0) g_len[b] = cnt;
}

// ---------------------------------------------------------------------------
// Generic batched SGEMM: C = A * B (TRANSB=false, B is [K,N] row-major)
//                        C = A * B^T (TRANSB=true, B is [N,K] row-major)
// Tiles: BM=BN=128, BK=8, 256 threads, 8x8 per thread.
// All dims divisible by 128/8 for this problem -> no bounds checks.
// ---------------------------------------------------------------------------
template <bool TRANSB>
__global__ __launch_bounds__(256) void sgemm_k(
    const float* __restrict__ A, const float* __restrict__ B, float* __restrict__ C,
    int M, int N, int K, size_t sA, size_t sB, size_t sC)
{
    __shared__ float As[8][128];
    __shared__ float Bs[8][128];

    const int bz = blockIdx.z;
    A += (size_t)bz * sA;
    B += (size_t)bz * sB;
    C += (size_t)bz * sC;

    const int m0 = blockIdx.y * 128;
    const int n0 = blockIdx.x * 128;
    const int tid = threadIdx.x;
    const int tx = tid & 15;   // 0..15 -> col group
    const int ty = tid >> 4;   // 0..15 -> row group

    const int ar = tid >> 1;         // 0..127
    const int ac = (tid & 1) * 4;    // 0 or 4

    float acc[8][8];
    #pragma unroll
    for (int i = 0; i < 8; i++)
        #pragma unroll
        for (int j = 0; j < 8; j++) acc[i][j] = 0.f;

    for (int k0 = 0; k0 < K; k0 += 8) {
        // A tile: [128 rows x 8 k], store transposed As[k][m]
        float4 av = *(const float4*)(A + (size_t)(m0 + ar) * K + k0 + ac);
        As[ac + 0][ar] = av.x; As[ac + 1][ar] = av.y;
        As[ac + 2][ar] = av.z; As[ac + 3][ar] = av.w;

        if (TRANSB) {
            // B is [N,K]; Bs[k][n] = B[n0+n][k0+k]
            float4 bv = *(const float4*)(B + (size_t)(n0 + ar) * K + k0 + ac);
            Bs[ac + 0][ar] = bv.x; Bs[ac + 1][ar] = bv.y;
            Bs[ac + 2][ar] = bv.z; Bs[ac + 3][ar] = bv.w;
        } else {
            const int br = tid >> 5;         // 0..7
            const int bc = (tid & 31) * 4;   // 0..124
            float4 bv = *(const float4*)(B + (size_t)(k0 + br) * N + n0 + bc);
            *(float4*)&Bs[br][bc] = bv;
        }
        __syncthreads();

        #pragma unroll
        for (int k = 0; k < 8; k++) {
            float a[8], b[8];
            *(float4*)&a[0] = *(const float4*)&As[k][ty * 8];
            *(float4*)&a[4] = *(const float4*)&As[k][ty * 8 + 4];
            *(float4*)&b[0] = *(const float4*)&Bs[k][tx * 8];
            *(float4*)&b[4] = *(const float4*)&Bs[k][tx * 8 + 4];
            #pragma unroll
            for (int i = 0; i < 8; i++)
                #pragma unroll
                for (int j = 0; j < 8; j++) acc[i][j] += a[i] * b[j];
        }
        __syncthreads();
    }

    #pragma unroll
    for (int i = 0; i < 8; i++) {
        float* crow = C + (size_t)(m0 + ty * 8 + i) * N + n0 + tx * 8;
        *(float4*)(crow + 0) = make_float4(acc[i][0], acc[i][1], acc[i][2], acc[i][3]);
        *(float4*)(crow + 4) = make_float4(acc[i][4], acc[i][5], acc[i][6], acc[i][7]);
    }
}

// ---------------------------------------------------------------------------
// Row softmax over s < len of S/8 (in place), zero the masked tail so the PV
// GEMM can run dense over K = NT. Padded query rows come out uniform 1/len,
// matching the reference.
// ---------------------------------------------------------------------------
__global__ __launch_bounds__(256) void softmax_k(float* __restrict__ S,
                                                 const int* __restrict__ lens)
{
    const int row = blockIdx.x;           // 0 .. NB*NT-1
    const int b = row >> 11;              // NT = 2048
    const int len = lens[b];
    float* p = S + (size_t)row * NT;
    const int tid = threadIdx.x;
    __shared__ float red[256];

    float m = -1e30f;
    for (int s = tid; s < len; s += 256) m = fmaxf(m, p[s]);
    red[tid] = m; __syncthreads();
    #pragma unroll
    for (int off = 128; off > 0; off >>= 1) {
        if (tid < off) red[tid] = fmaxf(red[tid], red[tid + off]);
        __syncthreads();
    }
    m = red[0]; __syncthreads();

    float sum = 0.f;
    for (int s = tid; s < len; s += 256) {
        float e = __expf((p[s] - m) * 0.125f);   // 1/sqrt(64) = 1/8
        p[s] = e;
        sum += e;
    }
    red[tid] = sum; __syncthreads();
    #pragma unroll
    for (int off = 128; off > 0; off >>= 1) {
        if (tid < off) red[tid] += red[tid + off];
        __syncthreads();
    }
    const float inv = 1.f / red[0];

    for (int s = tid; s < len; s += 256) p[s] *= inv;
    for (int s = len + tid; s < NT; s += 256) p[s] = 0.f;
}

// ---------------------------------------------------------------------------
extern "C" void kernel_launch(void* const* d_in, const int* in_sizes, int n_in,
                              void* d_out, int out_size)
{
    const float* x  = (const float*)d_in[0];
    const float* Wq = (const float*)d_in[1];
    const float* Wk = (const float*)d_in[2];
    const float* Wv = (const float*)d_in[3];
    float* out = (float*)d_out;

    float *Q, *K, *V, *S;
    int* lens;
    cudaGetSymbolAddress((void**)&Q, g_Q);
    cudaGetSymbolAddress((void**)&K, g_K);
    cudaGetSymbolAddress((void**)&V, g_V);
    cudaGetSymbolAddress((void**)&S, g_S);
    cudaGetSymbolAddress((void**)&lens, g_len);

    // 1) padding lengths
    len_k<<<NB, 256>>>(x);

    // 2) QKV projections: [16384,1024] x [1024,1024]
    dim3 blk(256);
    dim3 g_qkv(ND / 128, (NB * NT) / 128, 1);
    sgemm_k<false><<<g_qkv, blk>>>(x, Wq, Q, NB * NT, ND, NE, 0, 0, 0);
    sgemm_k<false><<<g_qkv, blk>>>(x, Wk, K, NB * NT, ND, NE, 0, 0, 0);
    sgemm_k<false><<<g_qkv, blk>>>(x, Wv, V, NB * NT, ND, NE, 0, 0, 0);

    // 3) energy = Q K^T per batch: [2048,1024] x [2048,1024]^T
    dim3 g_e(NT / 128, NT / 128, NB);
    sgemm_k<true><<<g_e, blk>>>(Q, K, S, NT, NT, ND,
                                (size_t)NT * ND, (size_t)NT * ND, (size_t)NT * NT);

    // 4) masked softmax over keys (in place, zeroes masked tail)
    softmax_k<<<NB * NT, 256>>>(S, lens);

    // 5) out = P V per batch: [2048,2048] x [2048,1024]
    dim3 g_o(ND / 128, NT / 128, NB);
    sgemm_k<false><<<g_o, blk>>>(S, V, out, NT, ND, NT,
                                 (size_t)NT * NT, (size_t)NT * ND, (size_t)NT * ND);
}

// round 2
// speedup vs baseline: 2.3006x; 2.3006x over previous
#include <cuda_runtime.h>
#include <cuda_bf16.h>
#include <cstdint>

using bf16 = __nv_bfloat16;
using bf162 = __nv_bfloat162;

#define NB 8
#define NT 2048
#define NE 1024
#define ND 1024

constexpr size_t SZ_X = (size_t)NB * NT * NE;   // 16M elems
constexpr size_t SZ_W = (size_t)NE * ND;        // 1M elems
constexpr size_t SZ_S = (size_t)NB * NT * NT;   // 33.5M elems

// ---- static scratch pool (no allocation allowed) ----
constexpr size_t OFF_XH  = 0;
constexpr size_t OFF_XL  = OFF_XH  + SZ_X * 2;
constexpr size_t OFF_WQH = OFF_XL  + SZ_X * 2;
constexpr size_t OFF_WQL = OFF_WQH + SZ_W * 2;
constexpr size_t OFF_WKH = OFF_WQL + SZ_W * 2;
constexpr size_t OFF_WKL = OFF_WKH + SZ_W * 2;
constexpr size_t OFF_WVH = OFF_WKL + SZ_W * 2;
constexpr size_t OFF_WVL = OFF_WVH + SZ_W * 2;
constexpr size_t OFF_QH  = OFF_WVL + SZ_W * 2;
constexpr size_t OFF_QL  = OFF_QH  + SZ_X * 2;
constexpr size_t OFF_KH  = OFF_QL  + SZ_X * 2;
constexpr size_t OFF_KL  = OFF_KH  + SZ_X * 2;
constexpr size_t OFF_VTH = OFF_KL  + SZ_X * 2;
constexpr size_t OFF_VTL = OFF_VTH + SZ_X * 2;
constexpr size_t OFF_S   = OFF_VTL + SZ_X * 2;
constexpr size_t OFF_PH  = OFF_S   + SZ_S * 4;
constexpr size_t OFF_PL  = OFF_PH  + SZ_S * 2;
constexpr size_t POOL_SZ = OFF_PL  + SZ_S * 2;

__device__ __align__(256) unsigned char g_pool[POOL_SZ];
__device__ int g_len[NB];

// ---------------------------------------------------------------------------
__device__ __forceinline__ void split2(float v, bf16& h, bf16& l) {
    h = __float2bfloat16(v);
    l = __float2bfloat16(v - __bfloat162float(h));
}

__device__ __forceinline__ void cp_async16(uint32_t dst, const void* src) {
    asm volatile("cp.async.cg.shared.global [%0], [%1], 16;\n"
                 :: "r"(dst), "l"(src) : "memory");
}

__device__ __forceinline__ void mma_bf16(float* c, const uint32_t* a, const uint32_t* b) {
    asm volatile(
        "mma.sync.aligned.m16n8k16.row.col.f32.bf16.bf16.f32 "
        "{%0,%1,%2,%3}, {%4,%5,%6,%7}, {%8,%9}, {%0,%1,%2,%3};\n"
        : "+f"(c[0]), "+f"(c[1]), "+f"(c[2]), "+f"(c[3])
        : "r"(a[0]), "r"(a[1]), "r"(a[2]), "r"(a[3]), "r"(b[0]), "r"(b[1]));
}

// ---------------------------------------------------------------------------
// per-batch valid length = number of nonzero rows of x[b]
// ---------------------------------------------------------------------------
__global__ __launch_bounds__(256) void len_k(const float* __restrict__ x)
{
    const int b = blockIdx.x;
    __shared__ int cnt;
    if (threadIdx.x == 0) cnt = 0;
    __syncthreads();
    int local = 0;
    for (int t = threadIdx.x; t < NT; t += blockDim.x) {
        const float4* row = (const float4*)(x + ((size_t)b * NT + t) * NE);
        bool nz = false;
        #pragma unroll 4
        for (int e = 0; e < NE / 4; e++) {
            float4 v = row[e];
            if (v.x != 0.f || v.y != 0.f || v.z != 0.f || v.w != 0.f) { nz = true; break; }
        }
        if (nz) local++;
    }
    atomicAdd(&cnt, local);
    __syncthreads();
    if (threadIdx.x == 0) g_len[b] = cnt;
}

// ---------------------------------------------------------------------------
// elementwise fp32 -> (bf16 hi, bf16 lo), 4 elems/thread
// ---------------------------------------------------------------------------
__global__ __launch_bounds__(256) void split_k(const float* __restrict__ in,
                                               bf16* __restrict__ h, bf16* __restrict__ l,
                                               size_t n4)
{
    size_t i = (size_t)blockIdx.x * 256 + threadIdx.x;
    if (i >= n4) return;
    float4 v = ((const float4*)in)[i];
    bf16 h0, h1, h2, h3, l0, l1, l2, l3;
    split2(v.x, h0, l0); split2(v.y, h1, l1);
    split2(v.z, h2, l2); split2(v.w, h3, l3);
    bf162* hp = (bf162*)(h + i * 4);
    bf162* lp = (bf162*)(l + i * 4);
    bf162 a; a.x = h0; a.y = h1; hp[0] = a;
    a.x = h2; a.y = h3; hp[1] = a;
    a.x = l0; a.y = l1; lp[0] = a;
    a.x = l2; a.y = l3; lp[1] = a;
}

// ---------------------------------------------------------------------------
// W [E][N] fp32 -> transposed split Wt[n][e] (hi, lo) via smem tile
// ---------------------------------------------------------------------------
__global__ __launch_bounds__(256) void trsplit_k(const float* __restrict__ W,
                                                 bf16* __restrict__ Th, bf16* __restrict__ Tl)
{
    __shared__ float tile[32][33];
    const int bn = blockIdx.x * 32;   // n
    const int be = blockIdx.y * 32;   // e
    const int tx = threadIdx.x, ty = threadIdx.y;   // 32 x 8
    #pragma unroll
    for (int r = 0; r < 4; r++)
        tile[ty + r * 8][tx] = W[(size_t)(be + ty + r * 8) * ND + bn + tx];
    __syncthreads();
    #pragma unroll
    for (int r = 0; r < 4; r++) {
        float v = tile[tx][ty + r * 8];
        bf16 h, l; split2(v, h, l);
        size_t o = (size_t)(bn + ty + r * 8) * NE + be + tx;
        Th[o] = h; Tl[o] = l;
    }
}

// ---------------------------------------------------------------------------
// TN GEMM with bf16 hi/lo 3-product emulation.
// C[m][n] = sum_k A[m][k] * B[n][k], A,B given as (hi,lo) bf16.
// Tile 128x128x32, 256 threads (8 warps: 2 m x 4 n), cp.async double buffer.
// EPI: 0 = fp32 C; 1 = split bf16 (Ch,Cl); 2 = split transposed per-batch (V -> Vt[b][n][t])
// ---------------------------------------------------------------------------
constexpr int SK = 40;          // smem row stride in bf16 elems (32 + 8 pad)
constexpr int STAGE_B = 4 * 128 * SK * 2;   // 40960 bytes per stage
constexpr int SMEM_B = 2 * STAGE_B;         // 81920

template<int EPI>
__global__ __launch_bounds__(256) void gemm3(
    const bf16* __restrict__ Ah, const bf16* __restrict__ Al,
    const bf16* __restrict__ Bh, const bf16* __restrict__ Bl,
    float* __restrict__ C, bf16* __restrict__ Ch, bf16* __restrict__ Cl,
    int M, int N, int K, size_t sA, size_t sB, size_t sC)
{
    extern __shared__ char sm[];
    const int z = blockIdx.z;
    Ah += z * sA; Al += z * sA;
    Bh += z * sB; Bl += z * sB;

    const int m0 = blockIdx.y * 128;
    const int n0 = blockIdx.x * 128;
    const int tid = threadIdx.x;
    const int wid = tid >> 5, lane = tid & 31;
    const int wm = (wid & 1) * 64;        // warp m offset
    const int wn = (wid >> 1) * 32;       // warp n offset
    const int g = lane >> 2, tg = lane & 3;

    float c[4][4][4];
    #pragma unroll
    for (int i = 0; i < 4; i++)
        #pragma unroll
        for (int j = 0; j < 4; j++)
            #pragma unroll
            for (int t = 0; t < 4; t++) c[i][j][t] = 0.f;

    // copy-role indices: 256 threads, each copies 2x16B per matrix per stage
    const int crow = tid >> 1;          // 0..127
    const int chalf = tid & 1;          // 0,1 -> 32B halves of 64B row
    const size_t aoff = (size_t)(m0 + crow) * K + chalf * 16;
    const size_t boff = (size_t)(n0 + crow) * K + chalf * 16;
    const uint32_t smbase = (uint32_t)__cvta_generic_to_shared(sm);
    const uint32_t dbase = crow * (SK * 2) + chalf * 32;

    auto issue = [&](int s, int k0) {
        uint32_t d = smbase + s * STAGE_B + dbase;
        const bf16* p;
        p = Ah + aoff + k0; cp_async16(d,               p); cp_async16(d + 16,               p + 8);
        p = Al + aoff + k0; cp_async16(d + 10240,       p); cp_async16(d + 10240 + 16,       p + 8);
        p = Bh + boff + k0; cp_async16(d + 20480,       p); cp_async16(d + 20480 + 16,       p + 8);
        p = Bl + boff + k0; cp_async16(d + 30720,       p); cp_async16(d + 30720 + 16,       p + 8);
        asm volatile("cp.async.commit_group;\n" ::: "memory");
    };

    const int nk = K / 32;
    issue(0, 0);
    for (int i = 0; i < nk; i++) {
        if (i + 1 < nk) {
            issue((i + 1) & 1, (i + 1) * 32);
            asm volatile("cp.async.wait_group 1;\n" ::: "memory");
        } else {
            asm volatile("cp.async.wait_group 0;\n" ::: "memory");
        }
        __syncthreads();

        const bf16* As_h = (const bf16*)(sm + (i & 1) * STAGE_B);
        const bf16* As_l = As_h + 128 * SK;
        const bf16* Bs_h = As_h + 2 * 128 * SK;
        const bf16* Bs_l = As_h + 3 * 128 * SK;

        #pragma unroll
        for (int ks = 0; ks < 32; ks += 16) {
            uint32_t bh[4][2], bl[4][2], a[4][4];
            #pragma unroll
            for (int nt = 0; nt < 4; nt++) {
                const bf16* p = Bs_h + (wn + nt * 8 + g) * SK + ks + tg * 2;
                bh[nt][0] = *(const uint32_t*)p;
                bh[nt][1] = *(const uint32_t*)(p + 8);
                const bf16* q = Bs_l + (wn + nt * 8 + g) * SK + ks + tg * 2;
                bl[nt][0] = *(const uint32_t*)q;
                bl[nt][1] = *(const uint32_t*)(q + 8);
            }
            #pragma unroll
            for (int mt = 0; mt < 4; mt++) {
                const bf16* p = As_h + (wm + mt * 16 + g) * SK + ks + tg * 2;
                a[mt][0] = *(const uint32_t*)p;
                a[mt][1] = *(const uint32_t*)(p + 8 * SK);
                a[mt][2] = *(const uint32_t*)(p + 8);
                a[mt][3] = *(const uint32_t*)(p + 8 * SK + 8);
            }
            #pragma unroll
            for (int mt = 0; mt < 4; mt++)
                #pragma unroll
                for (int nt = 0; nt < 4; nt++) {
                    mma_bf16(c[mt][nt], a[mt], bh[nt]);   // hi*hi
                    mma_bf16(c[mt][nt], a[mt], bl[nt]);   // hi*lo
                }
            #pragma unroll
            for (int mt = 0; mt < 4; mt++) {
                const bf16* p = As_l + (wm + mt * 16 + g) * SK + ks + tg * 2;
                a[mt][0] = *(const uint32_t*)p;
                a[mt][1] = *(const uint32_t*)(p + 8 * SK);
                a[mt][2] = *(const uint32_t*)(p + 8);
                a[mt][3] = *(const uint32_t*)(p + 8 * SK + 8);
            }
            #pragma unroll
            for (int mt = 0; mt < 4; mt++)
                #pragma unroll
                for (int nt = 0; nt < 4; nt++)
                    mma_bf16(c[mt][nt], a[mt], bh[nt]);   // lo*hi
        }
        __syncthreads();
    }

    // ----- epilogue -----
    if (EPI == 0) {
        float* Cz = C + z * sC;
        #pragma unroll
        for (int mt = 0; mt < 4; mt++) {
            const int row = m0 + wm + mt * 16 + g;
            #pragma unroll
            for (int nt = 0; nt < 4; nt++) {
                const int col = n0 + wn + nt * 8 + tg * 2;
                *(float2*)(Cz + (size_t)row * N + col)       = make_float2(c[mt][nt][0], c[mt][nt][1]);
                *(float2*)(Cz + (size_t)(row + 8) * N + col) = make_float2(c[mt][nt][2], c[mt][nt][3]);
            }
        }
    } else if (EPI == 1) {
        bf16* Hz = Ch + z * sC;
        bf16* Lz = Cl + z * sC;
        #pragma unroll
        for (int mt = 0; mt < 4; mt++) {
            const int row = m0 + wm + mt * 16 + g;
            #pragma unroll
            for (int nt = 0; nt < 4; nt++) {
                const int col = n0 + wn + nt * 8 + tg * 2;
                bf16 h0, h1, l0, l1;
                split2(c[mt][nt][0], h0, l0); split2(c[mt][nt][1], h1, l1);
                bf162 hv; hv.x = h0; hv.y = h1;
                bf162 lv; lv.x = l0; lv.y = l1;
                *(bf162*)(Hz + (size_t)row * N + col) = hv;
                *(bf162*)(Lz + (size_t)row * N + col) = lv;
                split2(c[mt][nt][2], h0, l0); split2(c[mt][nt][3], h1, l1);
                hv.x = h0; hv.y = h1; lv.x = l0; lv.y = l1;
                *(bf162*)(Hz + (size_t)(row + 8) * N + col) = hv;
                *(bf162*)(Lz + (size_t)(row + 8) * N + col) = lv;
            }
        }
    } else {  // EPI == 2 : V -> Vt[b][d][t] split
        #pragma unroll
        for (int mt = 0; mt < 4; mt++) {
            const int rowg = m0 + wm + mt * 16 + g;
            const int b = rowg >> 11;
            const int t = rowg & (NT - 1);
            const size_t base = (size_t)b * ND * NT;
            #pragma unroll
            for (int nt = 0; nt < 4; nt++) {
                const int col = n0 + wn + nt * 8 + tg * 2;
                bf16 h, l;
                split2(c[mt][nt][0], h, l);
                Ch[base + (size_t)col * NT + t] = h;       Cl[base + (size_t)col * NT + t] = l;
                split2(c[mt][nt][1], h, l);
                Ch[base + (size_t)(col + 1) * NT + t] = h; Cl[base + (size_t)(col + 1) * NT + t] = l;
                split2(c[mt][nt][2], h, l);
                Ch[base + (size_t)col * NT + t + 8] = h;   Cl[base + (size_t)col * NT + t + 8] = l;
                split2(c[mt][nt][3], h, l);
                Ch[base + (size_t)(col + 1) * NT + t + 8] = h; Cl[base + (size_t)(col + 1) * NT + t + 8] = l;
            }
        }
    }
}

// ---------------------------------------------------------------------------
// masked row softmax: S fp32 -> split bf16 P (hi,lo); zero tail s >= len.
// ---------------------------------------------------------------------------
__global__ __launch_bounds__(256) void softmax_split_k(const float* __restrict__ S,
                                                       bf16* __restrict__ Ph,
                                                       bf16* __restrict__ Pl,
                                                       const int* __restrict__ lens)
{
    const int row = blockIdx.x;
    const int b = row >> 11;
    const int len = lens[b];
    const float* p = S + (size_t)row * NT;
    bf16* ph = Ph + (size_t)row * NT;
    bf16* pl = Pl + (size_t)row * NT;
    const int tid = threadIdx.x;
    __shared__ float red[256];

    float m = -1e30f;
    for (int s = tid; s < len; s += 256) m = fmaxf(m, p[s]);
    red[tid] = m; __syncthreads();
    #pragma unroll
    for (int off = 128; off > 0; off >>= 1) {
        if (tid < off) red[tid] = fmaxf(red[tid], red[tid + off]);
        __syncthreads();
    }
    m = red[0]; __syncthreads();

    float sum = 0.f;
    for (int s = tid; s < len; s += 256)
        sum += __expf((p[s] - m) * 0.125f);
    red[tid] = sum; __syncthreads();
    #pragma unroll
    for (int off = 128; off > 0; off >>= 1) {
        if (tid < off) red[tid] += red[tid + off];
        __syncthreads();
    }
    const float inv = 1.f / red[0];

    for (int s = tid; s < len; s += 256) {
        float v = __expf((p[s] - m) * 0.125f) * inv;
        bf16 h, l; split2(v, h, l);
        ph[s] = h; pl[s] = l;
    }
    const bf16 z0 = __float2bfloat16(0.f);
    for (int s = len + tid; s < NT; s += 256) { ph[s] = z0; pl[s] = z0; }
}

// ---------------------------------------------------------------------------
extern "C" void kernel_launch(void* const* d_in, const int* in_sizes, int n_in,
                              void* d_out, int out_size)
{
    const float* x  = (const float*)d_in[0];
    const float* Wq = (const float*)d_in[1];
    const float* Wk = (const float*)d_in[2];
    const float* Wv = (const float*)d_in[3];
    float* out = (float*)d_out;

    unsigned char* pool;
    int* lens;
    cudaGetSymbolAddress((void**)&pool, g_pool);
    cudaGetSymbolAddress((void**)&lens, g_len);

    bf16* xh  = (bf16*)(pool + OFF_XH);
    bf16* xl  = (bf16*)(pool + OFF_XL);
    bf16* wqh = (bf16*)(pool + OFF_WQH);
    bf16* wql = (bf16*)(pool + OFF_WQL);
    bf16* wkh = (bf16*)(pool + OFF_WKH);
    bf16* wkl = (bf16*)(pool + OFF_WKL);
    bf16* wvh = (bf16*)(pool + OFF_WVH);
    bf16* wvl = (bf16*)(pool + OFF_WVL);
    bf16* Qh  = (bf16*)(pool + OFF_QH);
    bf16* Ql  = (bf16*)(pool + OFF_QL);
    bf16* Kh  = (bf16*)(pool + OFF_KH);
    bf16* Kl  = (bf16*)(pool + OFF_KL);
    bf16* Vth = (bf16*)(pool + OFF_VTH);
    bf16* Vtl = (bf16*)(pool + OFF_VTL);
    float* S  = (float*)(pool + OFF_S);
    bf16* Ph  = (bf16*)(pool + OFF_PH);
    bf16* Pl  = (bf16*)(pool + OFF_PL);

    static bool attr_done = false;
    if (!attr_done) {
        cudaFuncSetAttribute(gemm3<0>, cudaFuncAttributeMaxDynamicSharedMemorySize, SMEM_B);
        cudaFuncSetAttribute(gemm3<1>, cudaFuncAttributeMaxDynamicSharedMemorySize, SMEM_B);
        cudaFuncSetAttribute(gemm3<2>, cudaFuncAttributeMaxDynamicSharedMemorySize, SMEM_B);
        attr_done = true;
    }

    // 1) lengths + splits
    len_k<<<NB, 256>>>(x);
    split_k<<<(int)(SZ_X / 4 / 256), 256>>>(x, xh, xl, SZ_X / 4);
    dim3 tg(32, 32), tb(32, 8);
    trsplit_k<<<tg, tb>>>(Wq, wqh, wql);
    trsplit_k<<<tg, tb>>>(Wk, wkh, wkl);
    trsplit_k<<<tg, tb>>>(Wv, wvh, wvl);

    // 2) QKV projections: M=16384, N=1024, K=1024 (TN: Wt is [n][k])
    dim3 blk(256);
    dim3 gq(ND / 128, (NB * NT) / 128, 1);
    gemm3<1><<<gq, blk, SMEM_B>>>(xh, xl, wqh, wql, nullptr, Qh, Ql,
                                  NB * NT, ND, NE, 0, 0, 0);
    gemm3<1><<<gq, blk, SMEM_B>>>(xh, xl, wkh, wkl, nullptr, Kh, Kl,
                                  NB * NT, ND, NE, 0, 0, 0);
    gemm3<2><<<gq, blk, SMEM_B>>>(xh, xl, wvh, wvl, nullptr, Vth, Vtl,
                                  NB * NT, ND, NE, 0, 0, 0);

    // 3) energy = Q K^T per batch: M=N=2048, K=1024 (TN: K is [t][k])
    dim3 ge(NT / 128, NT / 128, NB);
    gemm3<0><<<ge, blk, SMEM_B>>>(Qh, Ql, Kh, Kl, S, nullptr, nullptr,
                                  NT, NT, ND,
                                  (size_t)NT * ND, (size_t)NT * ND, (size_t)NT * NT);

    // 4) masked softmax -> split P
    softmax_split_k<<<NB * NT, 256>>>(S, Ph, Pl, lens);

    // 5) out = P V per batch: M=2048, N=1024, K=2048 (TN: Vt is [d][s])
    dim3 go(ND / 128, NT / 128, NB);
    gemm3<0><<<go, blk, SMEM_B>>>(Ph, Pl, Vth, Vtl, out, nullptr, nullptr,
                                  NT, ND, NT,
                                  (size_t)NT * NT, (size_t)ND * NT, (size_t)NT * ND);
}

// round 4
// speedup vs baseline: 2.8763x; 1.2502x over previous
#include <cuda_runtime.h>
#include <cuda_bf16.h>
#include <cstdint>

using bf16 = __nv_bfloat16;
using bf162 = __nv_bfloat162;

#define NB 8
#define NT 2048
#define NE 1024
#define ND 1024

constexpr size_t SZ_X = (size_t)NB * NT * NE;
constexpr size_t SZ_W = (size_t)NE * ND;
constexpr size_t SZ_S = (size_t)NB * NT * NT;

// ---- static scratch pool ----
constexpr size_t OFF_XH  = 0;
constexpr size_t OFF_XL  = OFF_XH  + SZ_X * 2;
constexpr size_t OFF_WQH = OFF_XL  + SZ_X * 2;
constexpr size_t OFF_WQL = OFF_WQH + SZ_W * 2;
constexpr size_t OFF_WKH = OFF_WQL + SZ_W * 2;
constexpr size_t OFF_WKL = OFF_WKH + SZ_W * 2;
constexpr size_t OFF_WVH = OFF_WKL + SZ_W * 2;
constexpr size_t OFF_WVL = OFF_WVH + SZ_W * 2;
constexpr size_t OFF_QH  = OFF_WVL + SZ_W * 2;
constexpr size_t OFF_QL  = OFF_QH  + SZ_X * 2;
constexpr size_t OFF_KH  = OFF_QL  + SZ_X * 2;
constexpr size_t OFF_KL  = OFF_KH  + SZ_X * 2;
constexpr size_t OFF_VTH = OFF_KL  + SZ_X * 2;
constexpr size_t OFF_VTL = OFF_VTH + SZ_X * 2;
constexpr size_t OFF_S   = OFF_VTL + SZ_X * 2;
constexpr size_t OFF_PH  = OFF_S   + SZ_S * 4;
constexpr size_t OFF_PL  = OFF_PH  + SZ_S * 2;
constexpr size_t POOL_SZ = OFF_PL  + SZ_S * 2;

__device__ __align__(256) unsigned char g_pool[POOL_SZ];
__device__ int g_len[NB];

// ---------------------------------------------------------------------------
__device__ __forceinline__ void split2(float v, bf16& h, bf16& l) {
    h = __float2bfloat16(v);
    l = __float2bfloat16(v - __bfloat162float(h));
}

__device__ __forceinline__ void cp_async16(uint32_t dst, const void* src) {
    asm volatile("cp.async.cg.shared.global [%0], [%1], 16;\n"
                 :: "r"(dst), "l"(src) : "memory");
}

__device__ __forceinline__ uint32_t swz(uint32_t off) {
    return off ^ ((off >> 3) & 0x70);
}

__device__ __forceinline__ void ldm4(uint32_t* r, uint32_t a) {
    asm volatile("ldmatrix.sync.aligned.m8n8.x4.shared.b16 {%0,%1,%2,%3}, [%4];"
                 : "=r"(r[0]), "=r"(r[1]), "=r"(r[2]), "=r"(r[3]) : "r"(a));
}

__device__ __forceinline__ void mma_bf16(float* c, const uint32_t* a, const uint32_t* b) {
    asm volatile(
        "mma.sync.aligned.m16n8k16.row.col.f32.bf16.bf16.f32 "
        "{%0,%1,%2,%3}, {%4,%5,%6,%7}, {%8,%9}, {%0,%1,%2,%3};\n"
        : "+f"(c[0]), "+f"(c[1]), "+f"(c[2]), "+f"(c[3])
        : "r"(a[0]), "r"(a[1]), "r"(a[2]), "r"(a[3]), "r"(b[0]), "r"(b[1]));
}

// ---------------------------------------------------------------------------
// per-batch valid length = number of nonzero rows of x[b]
// ---------------------------------------------------------------------------
__global__ __launch_bounds__(256) void len_k(const float* __restrict__ x)
{
    const int b = blockIdx.x;
    __shared__ int cnt;
    if (threadIdx.x == 0) cnt = 0;
    __syncthreads();
    int local = 0;
    for (int t = threadIdx.x; t < NT; t += blockDim.x) {
        const float4* row = (const float4*)(x + ((size_t)b * NT + t) * NE);
        bool nz = false;
        #pragma unroll 4
        for (int e = 0; e < NE / 4; e++) {
            float4 v = row[e];
            if (v.x != 0.f || v.y != 0.f || v.z != 0.f || v.w != 0.f) { nz = true; break; }
        }
        if (nz) local++;
    }
    atomicAdd(&cnt, local);
    __syncthreads();
    if (threadIdx.x == 0) g_len[b] = cnt;
}

// ---------------------------------------------------------------------------
__global__ __launch_bounds__(256) void split_k(const float* __restrict__ in,
                                               bf16* __restrict__ h, bf16* __restrict__ l,
                                               size_t n4)
{
    size_t i = (size_t)blockIdx.x * 256 + threadIdx.x;
    if (i >= n4) return;
    float4 v = ((const float4*)in)[i];
    bf16 h0, h1, h2, h3, l0, l1, l2, l3;
    split2(v.x, h0, l0); split2(v.y, h1, l1);
    split2(v.z, h2, l2); split2(v.w, h3, l3);
    bf162* hp = (bf162*)(h + i * 4);
    bf162* lp = (bf162*)(l + i * 4);
    bf162 a; a.x = h0; a.y = h1; hp[0] = a;
    a.x = h2; a.y = h3; hp[1] = a;
    a.x = l0; a.y = l1; lp[0] = a;
    a.x = l2; a.y = l3; lp[1] = a;
}

__global__ __launch_bounds__(256) void trsplit_k(const float* __restrict__ W,
                                                 bf16* __restrict__ Th, bf16* __restrict__ Tl)
{
    __shared__ float tile[32][33];
    const int bn = blockIdx.x * 32;
    const int be = blockIdx.y * 32;
    const int tx = threadIdx.x, ty = threadIdx.y;
    #pragma unroll
    for (int r = 0; r < 4; r++)
        tile[ty + r * 8][tx] = W[(size_t)(be + ty + r * 8) * ND + bn + tx];
    __syncthreads();
    #pragma unroll
    for (int r = 0; r < 4; r++) {
        float v = tile[tx][ty + r * 8];
        bf16 h, l; split2(v, h, l);
        size_t o = (size_t)(bn + ty + r * 8) * NE + be + tx;
        Th[o] = h; Tl[o] = l;
    }
}

// ---------------------------------------------------------------------------
// HMMA TN GEMM, 3-term bf16 hi/lo emulation, ldmatrix + SW128, Ktile 64.
// C[m][n] = sum_k A[m][k]*B[n][k].
// EPI: 0 fp32 C; 1 split bf16 (Ch,Cl); 2 split V-transpose via smem staging.
// mode bits: 1 = skip col block if n0 >= len[z]; 2 = K-loop bounded by len[z];
//            4 = skip row block if m0 >= len[z]; 8 = skip row block if (m0&2047) >= len[m0>>11]
// ---------------------------------------------------------------------------
constexpr int SUB = 128 * 128;          // 16 KB per operand subtile (128 rows x 128B)
constexpr int STAGE = 4 * SUB;          // 64 KB per stage
constexpr int SMEM_TOTAL = 2 * STAGE;   // 131072

template<int EPI>
__global__ __launch_bounds__(256) void gemm4(
    const bf16* __restrict__ Ah, const bf16* __restrict__ Al,
    const bf16* __restrict__ Bh, const bf16* __restrict__ Bl,
    float* __restrict__ C, bf16* __restrict__ Ch, bf16* __restrict__ Cl,
    int Kdim, int ldC, size_t sA, size_t sB, size_t sC,
    const int* __restrict__ lens, int mode)
{
    extern __shared__ __align__(128) char sm[];
    const int z = blockIdx.z;
    const int m0 = blockIdx.y * 128, n0 = blockIdx.x * 128;

    if (mode & 1) { if (n0 >= lens[z]) return; }
    if (mode & 4) { if (m0 >= lens[z]) return; }
    if (mode & 8) { if ((m0 & (NT - 1)) >= lens[m0 >> 11]) return; }

    int nkt = Kdim / 64;
    if (mode & 2) nkt = (lens[z] + 63) >> 6;

    Ah += z * sA; Al += z * sA;
    Bh += z * sB; Bl += z * sB;

    const int tid = threadIdx.x;
    const int wid = tid >> 5, lane = tid & 31;
    const int wm = (wid & 1) * 64;
    const int wn = (wid >> 1) * 32;

    // ldmatrix lane decode
    const int a_row = (lane & 7) + ((lane >> 3) & 1) * 8;
    const int a_chk = lane >> 4;
    const int b_row = (lane & 7) + (lane >> 4) * 8;
    const int b_chk = (lane >> 3) & 1;

    const uint32_t smb = (uint32_t)__cvta_generic_to_shared(sm);

    float c[4][4][4];
    #pragma unroll
    for (int i = 0; i < 4; i++)
        #pragma unroll
        for (int j = 0; j < 4; j++)
            #pragma unroll
            for (int t = 0; t < 4; t++) c[i][j][t] = 0.f;

    // cp.async roles: thread -> row (tid>>1), 4 chunks of 16B
    const int r = tid >> 1;
    const int c0 = (tid & 1) * 4;
    const size_t arow = (size_t)(m0 + r) * Kdim;
    const size_t brow = (size_t)(n0 + r) * Kdim;

    auto load_stage = [&](int buf, int k0) {
        const uint32_t sbase = smb + buf * STAGE;
        #pragma unroll
        for (int j = 0; j < 4; j++) {
            const int cc = c0 + j;
            const uint32_t so = swz(r * 128 + cc * 16);
            const size_t ko = (size_t)k0 + cc * 8;
            cp_async16(sbase + so,           Ah + arow + ko);
            cp_async16(sbase + SUB + so,     Al + arow + ko);
            cp_async16(sbase + 2 * SUB + so, Bh + brow + ko);
            cp_async16(sbase + 3 * SUB + so, Bl + brow + ko);
        }
        asm volatile("cp.async.commit_group;" ::: "memory");
    };

    load_stage(0, 0);

    for (int i = 0; i < nkt; i++) {
        if (i + 1 < nkt) {
            load_stage((i + 1) & 1, (i + 1) * 64);
            asm volatile("cp.async.wait_group 1;" ::: "memory");
        } else {
            asm volatile("cp.async.wait_group 0;" ::: "memory");
        }
        __syncthreads();

        const uint32_t ahb = smb + (i & 1) * STAGE;
        const uint32_t alb = ahb + SUB;
        const uint32_t bhb = ahb + 2 * SUB;
        const uint32_t blb = ahb + 3 * SUB;

        #pragma unroll
        for (int kc = 0; kc < 8; kc += 2) {        // 4 ks steps of K=16
            uint32_t bh[8], bl[8], a[4][4];
            {
                const uint32_t off0 = swz((wn + b_row) * 128 + (kc + b_chk) * 16);
                const uint32_t off1 = swz((wn + 16 + b_row) * 128 + (kc + b_chk) * 16);
                ldm4(bh + 0, bhb + off0); ldm4(bh + 4, bhb + off1);
                ldm4(bl + 0, blb + off0); ldm4(bl + 4, blb + off1);
            }
            #pragma unroll
            for (int mt = 0; mt < 4; mt++) {
                const uint32_t off = swz((wm + mt * 16 + a_row) * 128 + (kc + a_chk) * 16);
                ldm4(a[mt], ahb + off);
            }
            #pragma unroll
            for (int mt = 0; mt < 4; mt++)
                #pragma unroll
                for (int nt = 0; nt < 4; nt++) {
                    mma_bf16(c[mt][nt], a[mt], &bh[nt * 2]);   // hi*hi
                    mma_bf16(c[mt][nt], a[mt], &bl[nt * 2]);   // hi*lo
                }
            #pragma unroll
            for (int mt = 0; mt < 4; mt++) {
                const uint32_t off = swz((wm + mt * 16 + a_row) * 128 + (kc + a_chk) * 16);
                ldm4(a[mt], alb + off);
            }
            #pragma unroll
            for (int mt = 0; mt < 4; mt++)
                #pragma unroll
                for (int nt = 0; nt < 4; nt++)
                    mma_bf16(c[mt][nt], a[mt], &bh[nt * 2]);   // lo*hi
        }
        __syncthreads();
    }

    // ----- epilogue -----
    const int g = lane >> 2, tg = lane & 3;
    if (EPI == 0) {
        float* Cz = C + z * sC;
        #pragma unroll
        for (int mt = 0; mt < 4; mt++) {
            const int row = m0 + wm + mt * 16 + g;
            #pragma unroll
            for (int nt = 0; nt < 4; nt++) {
                const int col = n0 + wn + nt * 8 + tg * 2;
                *(float2*)(Cz + (size_t)row * ldC + col)       = make_float2(c[mt][nt][0], c[mt][nt][1]);
                *(float2*)(Cz + (size_t)(row + 8) * ldC + col) = make_float2(c[mt][nt][2], c[mt][nt][3]);
            }
        }
    } else if (EPI == 1) {
        #pragma unroll
        for (int mt = 0; mt < 4; mt++) {
            const int row = m0 + wm + mt * 16 + g;
            #pragma unroll
            for (int nt = 0; nt < 4; nt++) {
                const int col = n0 + wn + nt * 8 + tg * 2;
                bf16 h0, h1, l0, l1;
                split2(c[mt][nt][0], h0, l0); split2(c[mt][nt][1], h1, l1);
                bf162 hv; hv.x = h0; hv.y = h1;
                bf162 lv; lv.x = l0; lv.y = l1;
                *(bf162*)(Ch + (size_t)row * ldC + col) = hv;
                *(bf162*)(Cl + (size_t)row * ldC + col) = lv;
                split2(c[mt][nt][2], h0, l0); split2(c[mt][nt][3], h1, l1);
                hv.x = h0; hv.y = h1; lv.x = l0; lv.y = l1;
                *(bf162*)(Ch + (size_t)(row + 8) * ldC + col) = hv;
                *(bf162*)(Cl + (size_t)(row + 8) * ldC + col) = lv;
            }
        }
    } else {
        // EPI 2: transpose through smem, then coalesced split stores.
        float* smf = (float*)sm;                 // 128 x 132 fp32 (67.6 KB)
        #pragma unroll
        for (int mt = 0; mt < 4; mt++) {
            const int rr = wm + mt * 16 + g;
            #pragma unroll
            for (int nt = 0; nt < 4; nt++) {
                const int cc = wn + nt * 8 + tg * 2;
                smf[(size_t)cc * 132 + rr]           = c[mt][nt][0];
                smf[(size_t)(cc + 1) * 132 + rr]     = c[mt][nt][1];
                smf[(size_t)cc * 132 + rr + 8]       = c[mt][nt][2];
                smf[(size_t)(cc + 1) * 132 + rr + 8] = c[mt][nt][3];
            }
        }
        __syncthreads();
        const int b = m0 >> 11, t0 = m0 & (NT - 1);
        bf16* Hb = Ch + (size_t)b * ND * NT;
        bf16* Lb = Cl + (size_t)b * ND * NT;
        const int dsub = tid >> 6;           // 0..3
        const int tcol = tid & 63;           // 0..63
        #pragma unroll
        for (int it = 0; it < 32; it++) {
            const int d = it * 4 + dsub;
            float2 v = *(float2*)(smf + (size_t)d * 132 + tcol * 2);
            bf16 h0, h1, l0, l1;
            split2(v.x, h0, l0); split2(v.y, h1, l1);
            bf162 hv; hv.x = h0; hv.y = h1;
            bf162 lv; lv.x = l0; lv.y = l1;
            *(bf162*)(Hb + (size_t)(n0 + d) * NT + t0 + tcol * 2) = hv;
            *(bf162*)(Lb + (size_t)(n0 + d) * NT + t0 + tcol * 2) = lv;
        }
    }
}

// ---------------------------------------------------------------------------
// masked row softmax with smem row cache: S fp32 -> split bf16 P.
// Rows t >= len get the exact uniform 1/len over s<len (zero Q row case).
// ---------------------------------------------------------------------------
__global__ __launch_bounds__(256) void softmax_split_k(const float* __restrict__ S,
                                                       bf16* __restrict__ Ph,
                                                       bf16* __restrict__ Pl,
                                                       const int* __restrict__ lens)
{
    __shared__ float cache[NT];
    __shared__ float red[256];
    const int row = blockIdx.x;
    const int b = row >> 11;
    const int t = row & (NT - 1);
    const int len = lens[b];
    bf16* ph = Ph + (size_t)row * NT;
    bf16* pl = Pl + (size_t)row * NT;
    const int tid = threadIdx.x;
    const bf16 z0 = __float2bfloat16(0.f);

    if (t >= len) {
        // zero Q row -> zero logits -> uniform over valid keys
        const float v = 1.f / (float)len;
        bf16 h, l; split2(v, h, l);
        for (int s = tid; s < len; s += 256) { ph[s] = h; pl[s] = l; }
        for (int s = len + tid; s < NT; s += 256) { ph[s] = z0; pl[s] = z0; }
        return;
    }

    const float* p = S + (size_t)row * NT;

    float m = -1e30f;
    for (int s = tid; s < len; s += 256) {
        float v = p[s];
        cache[s] = v;
        m = fmaxf(m, v);
    }
    red[tid] = m; __syncthreads();
    #pragma unroll
    for (int off = 128; off > 0; off >>= 1) {
        if (tid < off) red[tid] = fmaxf(red[tid], red[tid + off]);
        __syncthreads();
    }
    m = red[0]; __syncthreads();

    float sum = 0.f;
    for (int s = tid; s < len; s += 256) {
        float e = __expf((cache[s] - m) * 0.125f);
        cache[s] = e;
        sum += e;
    }
    red[tid] = sum; __syncthreads();
    #pragma unroll
    for (int off = 128; off > 0; off >>= 1) {
        if (tid < off) red[tid] += red[tid + off];
        __syncthreads();
    }
    const float inv = 1.f / red[0];

    for (int s = tid; s < len; s += 256) {
        bf16 h, l; split2(cache[s] * inv, h, l);
        ph[s] = h; pl[s] = l;
    }
    for (int s = len + tid; s < NT; s += 256) { ph[s] = z0; pl[s] = z0; }
}

// ---------------------------------------------------------------------------
extern "C" void kernel_launch(void* const* d_in, const int* in_sizes, int n_in,
                              void* d_out, int out_size)
{
    const float* x  = (const float*)d_in[0];
    const float* Wq = (const float*)d_in[1];
    const float* Wk = (const float*)d_in[2];
    const float* Wv = (const float*)d_in[3];
    float* out = (float*)d_out;

    unsigned char* pool;
    int* lens;
    cudaGetSymbolAddress((void**)&pool, g_pool);
    cudaGetSymbolAddress((void**)&lens, g_len);

    bf16* xh  = (bf16*)(pool + OFF_XH);
    bf16* xl  = (bf16*)(pool + OFF_XL);
    bf16* wqh = (bf16*)(pool + OFF_WQH);
    bf16* wql = (bf16*)(pool + OFF_WQL);
    bf16* wkh = (bf16*)(pool + OFF_WKH);
    bf16* wkl = (bf16*)(pool + OFF_WKL);
    bf16* wvh = (bf16*)(pool + OFF_WVH);
    bf16* wvl = (bf16*)(pool + OFF_WVL);
    bf16* Qh  = (bf16*)(pool + OFF_QH);
    bf16* Ql  = (bf16*)(pool + OFF_QL);
    bf16* Kh  = (bf16*)(pool + OFF_KH);
    bf16* Kl  = (bf16*)(pool + OFF_KL);
    bf16* Vth = (bf16*)(pool + OFF_VTH);
    bf16* Vtl = (bf16*)(pool + OFF_VTL);
    float* S  = (float*)(pool + OFF_S);
    bf16* Ph  = (bf16*)(pool + OFF_PH);
    bf16* Pl  = (bf16*)(pool + OFF_PL);

    cudaFuncSetAttribute(gemm4<0>, cudaFuncAttributeMaxDynamicSharedMemorySize, SMEM_TOTAL);
    cudaFuncSetAttribute(gemm4<1>, cudaFuncAttributeMaxDynamicSharedMemorySize, SMEM_TOTAL);
    cudaFuncSetAttribute(gemm4<2>, cudaFuncAttributeMaxDynamicSharedMemorySize, SMEM_TOTAL);

    // 1) lengths + splits
    len_k<<<NB, 256>>>(x);
    split_k<<<(int)(SZ_X / 4 / 256), 256>>>(x, xh, xl, SZ_X / 4);
    dim3 tg(32, 32), tb(32, 8);
    trsplit_k<<<tg, tb>>>(Wq, wqh, wql);
    trsplit_k<<<tg, tb>>>(Wk, wkh, wkl);
    trsplit_k<<<tg, tb>>>(Wv, wvh, wvl);

    // 2) QKV projections: M=16384, N=1024, K=1024; skip fully-padded row blocks (mode 8)
    dim3 blk(256);
    dim3 gq(ND / 128, (NB * NT) / 128, 1);
    gemm4<1><<<gq, blk, SMEM_TOTAL>>>(xh, xl, wqh, wql, nullptr, Qh, Ql,
                                      NE, ND, 0, 0, 0, lens, 8);
    gemm4<1><<<gq, blk, SMEM_TOTAL>>>(xh, xl, wkh, wkl, nullptr, Kh, Kl,
                                      NE, ND, 0, 0, 0, lens, 8);
    gemm4<2><<<gq, blk, SMEM_TOTAL>>>(xh, xl, wvh, wvl, nullptr, Vth, Vtl,
                                      NE, ND, 0, 0, 0, lens, 8);

    // 3) energy = Q K^T per batch; skip masked row blocks (4) and col blocks (1)
    dim3 ge(NT / 128, NT / 128, NB);
    gemm4<0><<<ge, blk, SMEM_TOTAL>>>(Qh, Ql, Kh, Kl, S, nullptr, nullptr,
                                      ND, NT,
                                      (size_t)NT * ND, (size_t)NT * ND, (size_t)NT * NT,
                                      lens, 1 | 4);

    // 4) masked softmax -> split P (uniform rows for t >= len)
    softmax_split_k<<<NB * NT, 256>>>(S, Ph, Pl, lens);

    // 5) out = P V per batch, K-loop bounded by len (mode 2)
    dim3 go(ND / 128, NT / 128, NB);
    gemm4<0><<<go, blk, SMEM_TOTAL>>>(Ph, Pl, Vth, Vtl, out, nullptr, nullptr,
                                      NT, ND,
                                      (size_t)NT * NT, (size_t)ND * NT, (size_t)NT * ND,
                                      lens, 2);
}